// round 10
// baseline (speedup 1.0000x reference)
#include <cuda_runtime.h>
#include <cuda_bf16.h>
#include <cstdint>

// Problem constants (fixed by the dataset): N=1,000,000 points, C=64 channels, K=64 grid
#define KGRID   64
#define NCELLS  (KGRID * KGRID * KGRID)   // 262144
#define NMAX    1000064

// Scratch in __device__ globals (no allocation allowed)
__device__ int  g_counts[NCELLS];
__device__ int  g_cursor[NCELLS];     // bumped by reorder
__device__ int2 g_startcnt[NCELLS];   // packed {segment start, count} for gather
__device__ int  g_total;              // global bump allocator for segment bases
__device__ int  g_pidx[NMAX];
__device__ int  g_perm[NMAX];

__device__ __forceinline__ int cell_of(float x, float y, float z) {
    int ix = (int)floorf((x + 1.0f) * (KGRID * 0.5f));
    int iy = (int)floorf((y + 1.0f) * (KGRID * 0.5f));
    int iz = (int)floorf((z + 1.0f) * (KGRID * 0.5f));
    ix = min(max(ix, 0), KGRID - 1);
    iy = min(max(iy, 0), KGRID - 1);
    iz = min(max(iz, 0), KGRID - 1);
    return ix * (KGRID * KGRID) + iy * KGRID + iz;
}

// ---------------------------------------------------------------------------
// Kernel 1: voxel index per point + per-cell counts.
// 4 points per thread via three float4 loads (12 floats = 4 xyz triples).
// ---------------------------------------------------------------------------
__global__ void idx_kernel(const float4* __restrict__ pts4, int n4, int n) {
    int i4 = blockIdx.x * blockDim.x + threadIdx.x;
    if (i4 >= n4) return;
    int base = i4 * 4;

    if (base + 4 <= n) {
        float4 a = pts4[i4 * 3 + 0];   // x0 y0 z0 x1
        float4 b = pts4[i4 * 3 + 1];   // y1 z1 x2 y2
        float4 c = pts4[i4 * 3 + 2];   // z2 x3 y3 z3
        int c0 = cell_of(a.x, a.y, a.z);
        int c1 = cell_of(a.w, b.x, b.y);
        int c2 = cell_of(b.z, b.w, c.x);
        int c3 = cell_of(c.y, c.z, c.w);
        *(int4*)&g_pidx[base] = make_int4(c0, c1, c2, c3);
        atomicAdd(&g_counts[c0], 1);
        atomicAdd(&g_counts[c1], 1);
        atomicAdd(&g_counts[c2], 1);
        atomicAdd(&g_counts[c3], 1);
    } else {
        const float* p = (const float*)pts4;
        for (int i = base; i < n; i++) {
            int cc = cell_of(p[3 * i], p[3 * i + 1], p[3 * i + 2]);
            g_pidx[i] = cc;
            atomicAdd(&g_counts[cc], 1);
        }
    }
}

// ---------------------------------------------------------------------------
// Kernel 2: fused scan. Each block scans its 512 counts locally, then grabs
// its global base with ONE atomicAdd on g_total. Writes the reorder cursor
// AND the packed {start,count} record gather consumes with a single 8B load.
// ---------------------------------------------------------------------------
__global__ void scan_fused_kernel() {
    __shared__ int s[512];
    __shared__ int s_base;
    int t = threadIdx.x;
    int i = blockIdx.x * 512 + t;
    int v = g_counts[i];
    s[t] = v;
    __syncthreads();
    #pragma unroll
    for (int d = 1; d < 512; d <<= 1) {
        int add = (t >= d) ? s[t - d] : 0;
        __syncthreads();
        s[t] += add;
        __syncthreads();
    }
    if (t == 511) s_base = atomicAdd(&g_total, s[511]);   // block's segment base
    __syncthreads();
    int off = s_base + s[t] - v;                          // exclusive offset
    g_cursor[i]   = off;
    g_startcnt[i] = make_int2(off, v);
}

// ---------------------------------------------------------------------------
// Kernel 3: reorder — build permutation grouping point ids by cell.
// 4 points per thread, one int4 pidx load.
// ---------------------------------------------------------------------------
__global__ void reorder_kernel(int n4, int n) {
    int i4 = blockIdx.x * blockDim.x + threadIdx.x;
    if (i4 >= n4) return;
    int base = i4 * 4;

    if (base + 4 <= n) {
        int4 c = *(const int4*)&g_pidx[base];
        int p0 = atomicAdd(&g_cursor[c.x], 1);
        int p1 = atomicAdd(&g_cursor[c.y], 1);
        int p2 = atomicAdd(&g_cursor[c.z], 1);
        int p3 = atomicAdd(&g_cursor[c.w], 1);
        g_perm[p0] = base + 0;
        g_perm[p1] = base + 1;
        g_perm[p2] = base + 2;
        g_perm[p3] = base + 3;
    } else {
        for (int i = base; i < n; i++) {
            int cell = g_pidx[i];
            int pos = atomicAdd(&g_cursor[cell], 1);
            g_perm[pos] = i;
        }
    }
}

// ---------------------------------------------------------------------------
// Kernel 4: gather + mean. EIGHT threads per cell; thread q owns float4
// lanes q and q+8 (32B per point per thread -> 8 independent LDG.128 in
// flight in the unroll-4 body). Exact loads only (R7: padding regresses).
// Metadata is ONE 8B load (packed start/count). Feature loads use .cs.
// ---------------------------------------------------------------------------
__global__ void gather_kernel(const float4* __restrict__ feat4,
                              float4* __restrict__ out) {
    int gid = blockIdx.x * blockDim.x + threadIdx.x;   // NCELLS*8 threads
    int cell = gid >> 3;
    int q    = gid & 7;
    int2 sc  = g_startcnt[cell];
    int start = sc.x;
    int cnt   = sc.y;
    const float4* fq = feat4 + q;

    float4 acc0 = make_float4(0.f, 0.f, 0.f, 0.f);
    float4 acc1 = make_float4(0.f, 0.f, 0.f, 0.f);
    int j = 0;
    for (; j + 4 <= cnt; j += 4) {
        int p0 = g_perm[start + j + 0];
        int p1 = g_perm[start + j + 1];
        int p2 = g_perm[start + j + 2];
        int p3 = g_perm[start + j + 3];
        float4 a0 = __ldcs(fq + (size_t)p0 * 16);
        float4 a1 = __ldcs(fq + (size_t)p0 * 16 + 8);
        float4 b0 = __ldcs(fq + (size_t)p1 * 16);
        float4 b1 = __ldcs(fq + (size_t)p1 * 16 + 8);
        float4 c0 = __ldcs(fq + (size_t)p2 * 16);
        float4 c1 = __ldcs(fq + (size_t)p2 * 16 + 8);
        float4 d0 = __ldcs(fq + (size_t)p3 * 16);
        float4 d1 = __ldcs(fq + (size_t)p3 * 16 + 8);
        acc0.x += a0.x + b0.x + c0.x + d0.x;
        acc0.y += a0.y + b0.y + c0.y + d0.y;
        acc0.z += a0.z + b0.z + c0.z + d0.z;
        acc0.w += a0.w + b0.w + c0.w + d0.w;
        acc1.x += a1.x + b1.x + c1.x + d1.x;
        acc1.y += a1.y + b1.y + c1.y + d1.y;
        acc1.z += a1.z + b1.z + c1.z + d1.z;
        acc1.w += a1.w + b1.w + c1.w + d1.w;
    }
    if (j + 2 <= cnt) {
        int p0 = g_perm[start + j + 0];
        int p1 = g_perm[start + j + 1];
        float4 a0 = __ldcs(fq + (size_t)p0 * 16);
        float4 a1 = __ldcs(fq + (size_t)p0 * 16 + 8);
        float4 b0 = __ldcs(fq + (size_t)p1 * 16);
        float4 b1 = __ldcs(fq + (size_t)p1 * 16 + 8);
        acc0.x += a0.x + b0.x; acc0.y += a0.y + b0.y;
        acc0.z += a0.z + b0.z; acc0.w += a0.w + b0.w;
        acc1.x += a1.x + b1.x; acc1.y += a1.y + b1.y;
        acc1.z += a1.z + b1.z; acc1.w += a1.w + b1.w;
        j += 2;
    }
    if (j < cnt) {
        int p0 = g_perm[start + j];
        float4 a0 = __ldcs(fq + (size_t)p0 * 16);
        float4 a1 = __ldcs(fq + (size_t)p0 * 16 + 8);
        acc0.x += a0.x; acc0.y += a0.y; acc0.z += a0.z; acc0.w += a0.w;
        acc1.x += a1.x; acc1.y += a1.y; acc1.z += a1.z; acc1.w += a1.w;
    }

    float inv = (cnt > 0) ? (1.0f / (float)cnt) : 1.0f;
    acc0.x *= inv; acc0.y *= inv; acc0.z *= inv; acc0.w *= inv;
    acc1.x *= inv; acc1.y *= inv; acc1.z *= inv; acc1.w *= inv;
    out[(size_t)cell * 16 + q]     = acc0;   // empty cells correctly write 0
    out[(size_t)cell * 16 + q + 8] = acc1;
}

// ---------------------------------------------------------------------------
// Launcher
// inputs: d_in[0] = point_feat (N*64 f32), d_in[1] = points (N*3 f32),
//         d_in[2] = k (int, =64). out: (64,64,64,64) f32
// ---------------------------------------------------------------------------
extern "C" void kernel_launch(void* const* d_in, const int* in_sizes, int n_in,
                              void* d_out, int out_size) {
    const float4* pts4  = (const float4*)d_in[1];
    const float4* feat4 = (const float4*)d_in[0];
    float4* out = (float4*)d_out;

    int n  = in_sizes[1] / 3;        // number of points
    int n4 = (n + 3) / 4;            // 4 points per idx/reorder thread

    // zero the counts scratch (1 MB) and the bump allocator
    void* counts_ptr = nullptr;
    void* total_ptr  = nullptr;
    cudaGetSymbolAddress(&counts_ptr, g_counts);
    cudaGetSymbolAddress(&total_ptr,  g_total);
    cudaMemsetAsync(counts_ptr, 0, NCELLS * sizeof(int), 0);
    cudaMemsetAsync(total_ptr,  0, sizeof(int), 0);

    const int T = 256;
    idx_kernel<<<(n4 + T - 1) / T, T>>>(pts4, n4, n);
    scan_fused_kernel<<<NCELLS / 512, 512>>>();
    reorder_kernel<<<(n4 + T - 1) / T, T>>>(n4, n);
    gather_kernel<<<(NCELLS * 8) / T, T>>>(feat4, out);
}

// round 11
// speedup vs baseline: 1.1849x; 1.1849x over previous
#include <cuda_runtime.h>
#include <cuda_bf16.h>
#include <cstdint>

// Problem constants (fixed by the dataset): N=1,000,000 points, C=64 channels, K=64 grid
#define KGRID   64
#define NCELLS  (KGRID * KGRID * KGRID)   // 262144
#define NMAX    1000064

// Scratch in __device__ globals (no allocation allowed)
__device__ int  g_counts[NCELLS];
__device__ int  g_cursor[NCELLS];     // bumped by reorder
__device__ int2 g_startcnt[NCELLS];   // packed {segment start, count} for gather
__device__ int  g_total;              // global bump allocator for segment bases
__device__ int  g_pidx[NMAX];
__device__ int  g_perm[NMAX];

__device__ __forceinline__ int cell_of(float x, float y, float z) {
    int ix = (int)floorf((x + 1.0f) * (KGRID * 0.5f));
    int iy = (int)floorf((y + 1.0f) * (KGRID * 0.5f));
    int iz = (int)floorf((z + 1.0f) * (KGRID * 0.5f));
    ix = min(max(ix, 0), KGRID - 1);
    iy = min(max(iy, 0), KGRID - 1);
    iz = min(max(iz, 0), KGRID - 1);
    return ix * (KGRID * KGRID) + iy * KGRID + iz;
}

// ---------------------------------------------------------------------------
// Kernel 1: voxel index per point + per-cell counts.
// 4 points per thread via three float4 loads (12 floats = 4 xyz triples).
// ---------------------------------------------------------------------------
__global__ void idx_kernel(const float4* __restrict__ pts4, int n4, int n) {
    int i4 = blockIdx.x * blockDim.x + threadIdx.x;
    if (i4 >= n4) return;
    int base = i4 * 4;

    if (base + 4 <= n) {
        float4 a = pts4[i4 * 3 + 0];   // x0 y0 z0 x1
        float4 b = pts4[i4 * 3 + 1];   // y1 z1 x2 y2
        float4 c = pts4[i4 * 3 + 2];   // z2 x3 y3 z3
        int c0 = cell_of(a.x, a.y, a.z);
        int c1 = cell_of(a.w, b.x, b.y);
        int c2 = cell_of(b.z, b.w, c.x);
        int c3 = cell_of(c.y, c.z, c.w);
        *(int4*)&g_pidx[base] = make_int4(c0, c1, c2, c3);
        atomicAdd(&g_counts[c0], 1);
        atomicAdd(&g_counts[c1], 1);
        atomicAdd(&g_counts[c2], 1);
        atomicAdd(&g_counts[c3], 1);
    } else {
        const float* p = (const float*)pts4;
        for (int i = base; i < n; i++) {
            int cc = cell_of(p[3 * i], p[3 * i + 1], p[3 * i + 2]);
            g_pidx[i] = cc;
            atomicAdd(&g_counts[cc], 1);
        }
    }
}

// ---------------------------------------------------------------------------
// Kernel 2: fused scan. Each block scans its 512 counts locally, then grabs
// its global base with ONE atomicAdd on g_total. Writes the reorder cursor
// AND the packed {start,count} record gather consumes with a single 8B load.
// ---------------------------------------------------------------------------
__global__ void scan_fused_kernel() {
    __shared__ int s[512];
    __shared__ int s_base;
    int t = threadIdx.x;
    int i = blockIdx.x * 512 + t;
    int v = g_counts[i];
    s[t] = v;
    __syncthreads();
    #pragma unroll
    for (int d = 1; d < 512; d <<= 1) {
        int add = (t >= d) ? s[t - d] : 0;
        __syncthreads();
        s[t] += add;
        __syncthreads();
    }
    if (t == 511) s_base = atomicAdd(&g_total, s[511]);   // block's segment base
    __syncthreads();
    int off = s_base + s[t] - v;                          // exclusive offset
    g_cursor[i]   = off;
    g_startcnt[i] = make_int2(off, v);
}

// ---------------------------------------------------------------------------
// Kernel 3: reorder — build permutation grouping point ids by cell.
// 4 points per thread, one int4 pidx load.
// ---------------------------------------------------------------------------
__global__ void reorder_kernel(int n4, int n) {
    int i4 = blockIdx.x * blockDim.x + threadIdx.x;
    if (i4 >= n4) return;
    int base = i4 * 4;

    if (base + 4 <= n) {
        int4 c = *(const int4*)&g_pidx[base];
        int p0 = atomicAdd(&g_cursor[c.x], 1);
        int p1 = atomicAdd(&g_cursor[c.y], 1);
        int p2 = atomicAdd(&g_cursor[c.z], 1);
        int p3 = atomicAdd(&g_cursor[c.w], 1);
        g_perm[p0] = base + 0;
        g_perm[p1] = base + 1;
        g_perm[p2] = base + 2;
        g_perm[p3] = base + 3;
    } else {
        for (int i = base; i < n; i++) {
            int cell = g_pidx[i];
            int pos = atomicAdd(&g_cursor[cell], 1);
            g_perm[pos] = i;
        }
    }
}

// ---------------------------------------------------------------------------
// Kernel 4: gather + mean — R9 shape (the proven fastest): 16 threads per
// cell, thread q owns float4 lane q. Exact loads only (R7: padding
// regresses); unroll-4 + 2/1 tails; .cs on the zero-reuse feat stream.
// R10 lesson: do NOT trade occupancy for per-thread MLP — keep 32 regs,
// 16 threads/cell. Only R10 keeper: packed int2 metadata (one 8B load).
// ---------------------------------------------------------------------------
__global__ void __launch_bounds__(256, 8)
gather_kernel(const float4* __restrict__ feat4,
              float4* __restrict__ out) {
    int gid = blockIdx.x * blockDim.x + threadIdx.x;   // NCELLS*16 threads
    int cell = gid >> 4;
    int q    = gid & 15;
    int2 sc  = g_startcnt[cell];
    int start = sc.x;
    int cnt   = sc.y;
    const float4* fq = feat4 + q;

    float4 acc = make_float4(0.f, 0.f, 0.f, 0.f);
    int j = 0;
    for (; j + 4 <= cnt; j += 4) {
        int p0 = g_perm[start + j + 0];
        int p1 = g_perm[start + j + 1];
        int p2 = g_perm[start + j + 2];
        int p3 = g_perm[start + j + 3];
        float4 a = __ldcs(fq + (size_t)p0 * 16);
        float4 b = __ldcs(fq + (size_t)p1 * 16);
        float4 c = __ldcs(fq + (size_t)p2 * 16);
        float4 d = __ldcs(fq + (size_t)p3 * 16);
        acc.x += a.x + b.x + c.x + d.x;
        acc.y += a.y + b.y + c.y + d.y;
        acc.z += a.z + b.z + c.z + d.z;
        acc.w += a.w + b.w + c.w + d.w;
    }
    if (j + 2 <= cnt) {
        int p0 = g_perm[start + j + 0];
        int p1 = g_perm[start + j + 1];
        float4 a = __ldcs(fq + (size_t)p0 * 16);
        float4 b = __ldcs(fq + (size_t)p1 * 16);
        acc.x += a.x + b.x; acc.y += a.y + b.y;
        acc.z += a.z + b.z; acc.w += a.w + b.w;
        j += 2;
    }
    if (j < cnt) {
        int p0 = g_perm[start + j];
        float4 a = __ldcs(fq + (size_t)p0 * 16);
        acc.x += a.x; acc.y += a.y; acc.z += a.z; acc.w += a.w;
    }

    float inv = (cnt > 0) ? (1.0f / (float)cnt) : 1.0f;
    acc.x *= inv; acc.y *= inv; acc.z *= inv; acc.w *= inv;
    out[(size_t)cell * 16 + q] = acc;   // empty cells correctly write 0
}

// ---------------------------------------------------------------------------
// Launcher
// inputs: d_in[0] = point_feat (N*64 f32), d_in[1] = points (N*3 f32),
//         d_in[2] = k (int, =64). out: (64,64,64,64) f32
// ---------------------------------------------------------------------------
extern "C" void kernel_launch(void* const* d_in, const int* in_sizes, int n_in,
                              void* d_out, int out_size) {
    const float4* pts4  = (const float4*)d_in[1];
    const float4* feat4 = (const float4*)d_in[0];
    float4* out = (float4*)d_out;

    int n  = in_sizes[1] / 3;        // number of points
    int n4 = (n + 3) / 4;            // 4 points per idx/reorder thread

    // zero the counts scratch (1 MB) and the bump allocator
    void* counts_ptr = nullptr;
    void* total_ptr  = nullptr;
    cudaGetSymbolAddress(&counts_ptr, g_counts);
    cudaGetSymbolAddress(&total_ptr,  g_total);
    cudaMemsetAsync(counts_ptr, 0, NCELLS * sizeof(int), 0);
    cudaMemsetAsync(total_ptr,  0, sizeof(int), 0);

    const int T = 256;
    idx_kernel<<<(n4 + T - 1) / T, T>>>(pts4, n4, n);
    scan_fused_kernel<<<NCELLS / 512, 512>>>();
    reorder_kernel<<<(n4 + T - 1) / T, T>>>(n4, n);
    gather_kernel<<<(NCELLS * 16) / T, T>>>(feat4, out);
}

// round 12
// speedup vs baseline: 1.1880x; 1.0025x over previous
#include <cuda_runtime.h>
#include <cuda_bf16.h>
#include <cstdint>

// Problem constants (fixed by the dataset): N=1,000,000 points, C=64 channels, K=64 grid
#define KGRID    64
#define NCELLS   (KGRID * KGRID * KGRID)   // 262144
#define NMAX     1000064
#define NBLOCKS  592                       // 148 SMs x 4 resident CTAs (guaranteed by launch_bounds)
#define NTHREADS 256
#define NTOT     (NBLOCKS * NTHREADS)      // 151552 persistent threads
#define MAXIT    2                         // ceil((NMAX/4) / NTOT) = 2 point-groups per thread

// Scratch in __device__ globals (no allocation allowed)
__device__ int      g_counts[NCELLS];
__device__ int      g_cursor[NCELLS];     // bumped by reorder phase
__device__ int2     g_startcnt[NCELLS];   // packed {segment start, count} for gather
__device__ int      g_total;              // global bump allocator for segment bases
__device__ int      g_perm[NMAX];
__device__ unsigned g_bar_count;          // grid barrier state (replay-safe: gen is monotonic)
__device__ unsigned g_bar_gen;

__device__ __forceinline__ int cell_of(float x, float y, float z) {
    int ix = (int)floorf((x + 1.0f) * (KGRID * 0.5f));
    int iy = (int)floorf((y + 1.0f) * (KGRID * 0.5f));
    int iz = (int)floorf((z + 1.0f) * (KGRID * 0.5f));
    ix = min(max(ix, 0), KGRID - 1);
    iy = min(max(iy, 0), KGRID - 1);
    iz = min(max(iz, 0), KGRID - 1);
    return ix * (KGRID * KGRID) + iy * KGRID + iz;
}

// Sense-reversing grid barrier. Safe across graph replays: count always
// returns to 0 at release; gen only ever increments (wraps harmlessly).
__device__ __forceinline__ void grid_barrier() {
    __threadfence();
    __syncthreads();
    if (threadIdx.x == 0) {
        unsigned gen = atomicAdd(&g_bar_gen, 0u);
        unsigned arrived = atomicAdd(&g_bar_count, 1u) + 1u;
        if (arrived == NBLOCKS) {
            atomicExch(&g_bar_count, 0u);       // reset BEFORE release
            __threadfence();
            atomicAdd(&g_bar_gen, 1u);          // release
        } else {
            while (atomicAdd(&g_bar_gen, 0u) == gen) { }
        }
    }
    __syncthreads();
}

// ---------------------------------------------------------------------------
// Fused build kernel (persistent): zero -> histogram -> scan -> reorder.
// Cells computed in P1 are kept in REGISTERS and reused in P3 (no pidx array:
// saves 8 MB of traffic and two kernel launches). Replaces 2 memsets + 3
// kernels (and their launch gaps) with one launch + 3 grid barriers.
// ---------------------------------------------------------------------------
__global__ void __launch_bounds__(NTHREADS, 4)
build_kernel(const float4* __restrict__ pts4, int n) {
    const int tid = blockIdx.x * NTHREADS + threadIdx.x;
    __shared__ int s[NTHREADS];
    __shared__ int s_base;

    // ---- P0: zero counts + allocator ----
    for (int i = tid; i < NCELLS / 4; i += NTOT)
        ((int4*)g_counts)[i] = make_int4(0, 0, 0, 0);
    if (tid == 0) g_total = 0;
    grid_barrier();

    // ---- P1: histogram; keep each thread's cells in registers ----
    int n4 = (n + 3) >> 2;
    int cells[MAXIT][4];
    {
        int it = 0;
        for (int i4 = tid; i4 < n4 && it < MAXIT; i4 += NTOT, it++) {
            int base = i4 * 4;
            int c0, c1, c2, c3;
            if (base + 4 <= n) {
                float4 a = pts4[i4 * 3 + 0];   // x0 y0 z0 x1
                float4 b = pts4[i4 * 3 + 1];   // y1 z1 x2 y2
                float4 c = pts4[i4 * 3 + 2];   // z2 x3 y3 z3
                c0 = cell_of(a.x, a.y, a.z);
                c1 = cell_of(a.w, b.x, b.y);
                c2 = cell_of(b.z, b.w, c.x);
                c3 = cell_of(c.y, c.z, c.w);
            } else {
                const float* p = (const float*)pts4;
                c0 = (base + 0 < n) ? cell_of(p[3*(base+0)], p[3*(base+0)+1], p[3*(base+0)+2]) : -1;
                c1 = (base + 1 < n) ? cell_of(p[3*(base+1)], p[3*(base+1)+1], p[3*(base+1)+2]) : -1;
                c2 = (base + 2 < n) ? cell_of(p[3*(base+2)], p[3*(base+2)+1], p[3*(base+2)+2]) : -1;
                c3 = (base + 3 < n) ? cell_of(p[3*(base+3)], p[3*(base+3)+1], p[3*(base+3)+2]) : -1;
            }
            cells[it][0] = c0; cells[it][1] = c1;
            cells[it][2] = c2; cells[it][3] = c3;
            if (c0 >= 0) atomicAdd(&g_counts[c0], 1);
            if (c1 >= 0) atomicAdd(&g_counts[c1], 1);
            if (c2 >= 0) atomicAdd(&g_counts[c2], 1);
            if (c3 >= 0) atomicAdd(&g_counts[c3], 1);
        }
    }
    grid_barrier();

    // ---- P2: scan in 256-cell chunks; one g_total bump per chunk.
    // Segment order across chunks is atomic-arrival order — irrelevant:
    // gather only needs each cell's segment contiguous. ----
    {
        const int t = threadIdx.x;
        const int NCHUNK = NCELLS / NTHREADS;   // 1024
        for (int chunk = blockIdx.x; chunk < NCHUNK; chunk += NBLOCKS) {
            int i = chunk * NTHREADS + t;
            int v = __ldcg(&g_counts[i]);       // L2-coherent read (atomics wrote L2)
            s[t] = v;
            __syncthreads();
            #pragma unroll
            for (int d = 1; d < NTHREADS; d <<= 1) {
                int add = (t >= d) ? s[t - d] : 0;
                __syncthreads();
                s[t] += add;
                __syncthreads();
            }
            if (t == NTHREADS - 1) s_base = atomicAdd(&g_total, s[NTHREADS - 1]);
            __syncthreads();
            int off = s_base + s[t] - v;        // exclusive offset
            g_cursor[i]   = off;
            g_startcnt[i] = make_int2(off, v);
            __syncthreads();                    // protect s/s_base before next chunk
        }
    }
    grid_barrier();

    // ---- P3: reorder straight from the registers cached in P1 ----
    {
        int it = 0;
        for (int i4 = tid; i4 < n4 && it < MAXIT; i4 += NTOT, it++) {
            int base = i4 * 4;
            #pragma unroll
            for (int j = 0; j < 4; j++) {
                int c = cells[it][j];
                if (c >= 0) {
                    int pos = atomicAdd(&g_cursor[c], 1);
                    g_perm[pos] = base + j;
                }
            }
        }
    }
}

// ---------------------------------------------------------------------------
// Gather + mean — UNCHANGED from R11 (proven optimum): 16 threads per cell,
// thread q owns float4 lane q. Exact loads only (R7: padding regresses);
// unroll-4 + 2/1 tails; .cs on the zero-reuse feat stream; packed int2
// metadata; 32 regs / high occupancy (R10: never trade occupancy for MLP).
// ---------------------------------------------------------------------------
__global__ void __launch_bounds__(256, 8)
gather_kernel(const float4* __restrict__ feat4,
              float4* __restrict__ out) {
    int gid = blockIdx.x * blockDim.x + threadIdx.x;   // NCELLS*16 threads
    int cell = gid >> 4;
    int q    = gid & 15;
    int2 sc  = g_startcnt[cell];
    int start = sc.x;
    int cnt   = sc.y;
    const float4* fq = feat4 + q;

    float4 acc = make_float4(0.f, 0.f, 0.f, 0.f);
    int j = 0;
    for (; j + 4 <= cnt; j += 4) {
        int p0 = g_perm[start + j + 0];
        int p1 = g_perm[start + j + 1];
        int p2 = g_perm[start + j + 2];
        int p3 = g_perm[start + j + 3];
        float4 a = __ldcs(fq + (size_t)p0 * 16);
        float4 b = __ldcs(fq + (size_t)p1 * 16);
        float4 c = __ldcs(fq + (size_t)p2 * 16);
        float4 d = __ldcs(fq + (size_t)p3 * 16);
        acc.x += a.x + b.x + c.x + d.x;
        acc.y += a.y + b.y + c.y + d.y;
        acc.z += a.z + b.z + c.z + d.z;
        acc.w += a.w + b.w + c.w + d.w;
    }
    if (j + 2 <= cnt) {
        int p0 = g_perm[start + j + 0];
        int p1 = g_perm[start + j + 1];
        float4 a = __ldcs(fq + (size_t)p0 * 16);
        float4 b = __ldcs(fq + (size_t)p1 * 16);
        acc.x += a.x + b.x; acc.y += a.y + b.y;
        acc.z += a.z + b.z; acc.w += a.w + b.w;
        j += 2;
    }
    if (j < cnt) {
        int p0 = g_perm[start + j];
        float4 a = __ldcs(fq + (size_t)p0 * 16);
        acc.x += a.x; acc.y += a.y; acc.z += a.z; acc.w += a.w;
    }

    float inv = (cnt > 0) ? (1.0f / (float)cnt) : 1.0f;
    acc.x *= inv; acc.y *= inv; acc.z *= inv; acc.w *= inv;
    out[(size_t)cell * 16 + q] = acc;   // empty cells correctly write 0
}

// ---------------------------------------------------------------------------
// Launcher
// inputs: d_in[0] = point_feat (N*64 f32), d_in[1] = points (N*3 f32),
//         d_in[2] = k (int, =64). out: (64,64,64,64) f32
// ---------------------------------------------------------------------------
extern "C" void kernel_launch(void* const* d_in, const int* in_sizes, int n_in,
                              void* d_out, int out_size) {
    const float4* pts4  = (const float4*)d_in[1];
    const float4* feat4 = (const float4*)d_in[0];
    float4* out = (float4*)d_out;

    int n = in_sizes[1] / 3;   // number of points

    build_kernel<<<NBLOCKS, NTHREADS>>>(pts4, n);
    gather_kernel<<<(NCELLS * 16) / 256, 256>>>(feat4, out);
}